// round 1
// baseline (speedup 1.0000x reference)
#include <cuda_runtime.h>
#include <math.h>

#define N_NODES 2048
#define TXT     1386
#define HIDD    4096
#define CODE    64
#define XWORDS  44   // ceil(1386/32)

// ---------------- scratch (device globals; no allocation allowed) ----------
__device__ unsigned g_xb[N_NODES * XWORDS];          // bit-packed x
__device__ float    g_w[(size_t)N_NODES * N_NODES];  // unnormalized adj (0/1/2)
__device__ int      g_deg[N_NODES];
__device__ float    g_rinv[N_NODES];
__device__ float    g_P[(size_t)N_NODES * HIDD];     // h@W products
__device__ float    g_feat1[(size_t)N_NODES * HIDD]; // gc1 output
__device__ float    g_P3[(size_t)N_NODES * CODE];

// ---------------- K1: pack x rows into bits; zero degree -------------------
__global__ void pack_bits(const float* __restrict__ x) {
    int row = blockIdx.x;
    int w   = threadIdx.x;
    if (w == 0) g_deg[row] = 0;
    if (w < XWORDS) {
        unsigned bits = 0;
        int base = w * 32;
        #pragma unroll 8
        for (int b = 0; b < 32; b++) {
            int c = base + b;
            if (c < TXT && x[(size_t)row * TXT + c] != 0.0f) bits |= (1u << b);
        }
        g_xb[row * XWORDS + w] = bits;
    }
}

// ---------------- K2: adjacency via popcount + degree ----------------------
#define AT 64
__global__ void build_adj() {
    __shared__ unsigned aw[AT * XWORDS];
    __shared__ unsigned bw[AT * XWORDS];
    __shared__ int sdeg[AT];
    const int bi = blockIdx.y * AT;
    const int bj = blockIdx.x * AT;
    const int tid = threadIdx.x;

    for (int idx = tid; idx < AT * XWORDS; idx += 256) {
        int r = idx / XWORDS, c = idx % XWORDS;
        aw[idx] = g_xb[(bi + r) * XWORDS + c];
        bw[idx] = g_xb[(bj + r) * XWORDS + c];
    }
    if (tid < AT) sdeg[tid] = 0;
    __syncthreads();

    const int tx = tid % 16, ty = tid / 16;
    #pragma unroll
    for (int ii = 0; ii < 4; ii++) {
        const int i = ty * 4 + ii;
        int dsum = 0;
        #pragma unroll
        for (int jj = 0; jj < 4; jj++) {
            const int j = tx * 4 + jj;
            int cnt = 0;
            #pragma unroll 4
            for (int k = 0; k < XWORDS; k++)
                cnt += __popc(aw[i * XWORDS + k] & bw[j * XWORDS + k]);
            int wv = (cnt > 0 ? 1 : 0) + ((bi + i) == (bj + j) ? 1 : 0);
            g_w[(size_t)(bi + i) * N_NODES + (bj + j)] = (float)wv;
            dsum += wv;
        }
        atomicAdd(&sdeg[i], dsum);
    }
    __syncthreads();
    if (tid < AT) atomicAdd(&g_deg[bi + tid], sdeg[tid]);
}

// ---------------- K3: rinv = 1/deg  (deg >= 1 always) ----------------------
__global__ void compute_rinv() {
    int i = blockIdx.x * 256 + threadIdx.x;
    if (i < N_NODES) g_rinv[i] = 1.0f / (float)g_deg[i];
}

// ---------------- K4: P1 = x @ W1 (sparse binary rows) ---------------------
__global__ void xw1_kernel(const float* __restrict__ x, const float* __restrict__ W1) {
    __shared__ float xs[TXT];
    const int row = blockIdx.x;
    const int tid = threadIdx.x;
    for (int c = tid; c < TXT; c += 256) xs[c] = x[(size_t)row * TXT + c];
    __syncthreads();

    float acc[16];
    #pragma unroll
    for (int j = 0; j < 16; j++) acc[j] = 0.0f;

    for (int k = 0; k < TXT; k++) {
        if (xs[k] != 0.0f) {               // uniform across block
            const float* wr = W1 + (size_t)k * HIDD + tid;
            #pragma unroll
            for (int j = 0; j < 16; j++) acc[j] += wr[j * 256];
        }
    }
    float* out = g_P + (size_t)row * HIDD + tid;
    #pragma unroll
    for (int j = 0; j < 16; j++) out[j * 256] = acc[j];
}

// ---------------- generic tiled SGEMM with fused epilogue ------------------
// MODE 0: C = A@B
// MODE 1: C = rinv[row]*(A@B) + bias[col]
// MODE 2: C = relu(rinv[row]*(A@B) + bias[col])
// MODE 3: C = rinv[row]*(A@B) + bias[col];  C2 = tanh(C)
template<int V>
__device__ __forceinline__ void ldvec(float* d, const float* s) {
    if constexpr (V == 8) {
        *(float4*)d       = *(const float4*)s;
        *(float4*)(d + 4) = *(const float4*)(s + 4);
    } else if constexpr (V == 4) {
        *(float4*)d = *(const float4*)s;
    } else if constexpr (V == 2) {
        *(float2*)d = *(const float2*)s;
    } else {
        #pragma unroll
        for (int i = 0; i < V; i++) d[i] = s[i];
    }
}

template<int BM, int BN, int BK, int TM, int TN, int MODE>
__global__ __launch_bounds__(256)
void sgemm(const float* __restrict__ A, const float* __restrict__ B,
           float* __restrict__ C, float* __restrict__ C2,
           int M, int N, int K,
           const float* __restrict__ rowscale, const float* __restrict__ bias)
{
    static_assert((BM / TM) * (BN / TN) == 256, "need 256 threads");
    constexpr int ALOAD = BM * BK / 256;
    constexpr int BLOAD = BK * BN / 256;

    __shared__ float As[2][BK * BM];
    __shared__ float Bs[2][BK * BN];

    const int tid = threadIdx.x;
    const int bm  = blockIdx.y * BM;
    const int bn  = blockIdx.x * BN;
    const int tx  = tid % (BN / TN);
    const int ty  = tid / (BN / TN);

    // prologue: stage 0 directly global -> smem
    #pragma unroll
    for (int l = 0; l < ALOAD; l++) {
        int idx = tid + l * 256;
        int r = idx / BK, c = idx % BK;
        As[0][c * BM + r] = A[(size_t)(bm + r) * K + c];
    }
    #pragma unroll
    for (int l = 0; l < BLOAD; l++) {
        int idx = tid + l * 256;
        int r = idx / BN, c = idx % BN;
        Bs[0][r * BN + c] = B[(size_t)r * N + bn + c];
    }
    __syncthreads();

    float acc[TM * TN];
    #pragma unroll
    for (int i = 0; i < TM * TN; i++) acc[i] = 0.0f;

    float areg[ALOAD], breg[BLOAD];
    const int nk = K / BK;
    int st = 0;

    for (int kt = 0; kt < nk; kt++) {
        if (kt + 1 < nk) {
            const int k0 = (kt + 1) * BK;
            #pragma unroll
            for (int l = 0; l < ALOAD; l++) {
                int idx = tid + l * 256;
                int r = idx / BK, c = idx % BK;
                areg[l] = A[(size_t)(bm + r) * K + k0 + c];
            }
            #pragma unroll
            for (int l = 0; l < BLOAD; l++) {
                int idx = tid + l * 256;
                int r = idx / BN, c = idx % BN;
                breg[l] = B[(size_t)(k0 + r) * N + bn + c];
            }
        }
        #pragma unroll
        for (int kk = 0; kk < BK; kk++) {
            float fa[TM], fb[TN];
            ldvec<TM>(fa, &As[st][kk * BM + ty * TM]);
            ldvec<TN>(fb, &Bs[st][kk * BN + tx * TN]);
            #pragma unroll
            for (int i = 0; i < TM; i++)
                #pragma unroll
                for (int j = 0; j < TN; j++)
                    acc[i * TN + j] += fa[i] * fb[j];
        }
        if (kt + 1 < nk) {
            st ^= 1;
            #pragma unroll
            for (int l = 0; l < ALOAD; l++) {
                int idx = tid + l * 256;
                int r = idx / BK, c = idx % BK;
                As[st][c * BM + r] = areg[l];
            }
            #pragma unroll
            for (int l = 0; l < BLOAD; l++) {
                int idx = tid + l * 256;
                int r = idx / BN, c = idx % BN;
                Bs[st][r * BN + c] = breg[l];
            }
            __syncthreads();
        }
    }

    // epilogue
    const int row0 = bm + ty * TM;
    const int col0 = bn + tx * TN;
    #pragma unroll
    for (int i = 0; i < TM; i++) {
        float rs = 1.0f;
        if (MODE >= 1) rs = rowscale[row0 + i];
        #pragma unroll
        for (int j = 0; j < TN; j++) {
            float v = acc[i * TN + j];
            if (MODE >= 1) v = v * rs + bias[col0 + j];
            if (MODE == 2) v = fmaxf(v, 0.0f);
            size_t o = (size_t)(row0 + i) * N + col0 + j;
            C[o] = v;
            if (MODE == 3) C2[o] = tanhf(v);
        }
    }
}

// ---------------- launch ----------------------------------------------------
extern "C" void kernel_launch(void* const* d_in, const int* in_sizes, int n_in,
                              void* d_out, int out_size) {
    const float* x  = (const float*)d_in[0];
    const float* W1 = (const float*)d_in[1];
    const float* b1 = (const float*)d_in[2];
    const float* W2 = (const float*)d_in[3];
    const float* b2 = (const float*)d_in[4];
    const float* W3 = (const float*)d_in[5];
    const float* b3 = (const float*)d_in[6];

    float *w, *rinv, *P, *feat1, *P3;
    void* p;
    cudaGetSymbolAddress(&p, g_w);     w     = (float*)p;
    cudaGetSymbolAddress(&p, g_rinv);  rinv  = (float*)p;
    cudaGetSymbolAddress(&p, g_P);     P     = (float*)p;
    cudaGetSymbolAddress(&p, g_feat1); feat1 = (float*)p;
    cudaGetSymbolAddress(&p, g_P3);    P3    = (float*)p;

    float* featOut = (float*)d_out;
    float* hidOut  = featOut + (size_t)N_NODES * HIDD;
    float* codeOut = hidOut  + (size_t)N_NODES * CODE;

    // adjacency structure
    pack_bits<<<N_NODES, 64>>>(x);
    build_adj<<<dim3(N_NODES / AT, N_NODES / AT), 256>>>();
    compute_rinv<<<N_NODES / 256, 256>>>();

    // gc1: P1 = x@W1 (sparse); feat1 = rinv*(w@P1) + b1
    xw1_kernel<<<N_NODES, 256>>>(x, W1);
    sgemm<128, 128, 8, 8, 8, 1><<<dim3(HIDD / 128, N_NODES / 128), 256>>>(
        w, P, feat1, nullptr, N_NODES, HIDD, N_NODES, rinv, b1);

    // gc2: P2 = feat1@W2; feat = relu(rinv*(w@P2) + b2) -> d_out
    sgemm<128, 128, 8, 8, 8, 0><<<dim3(HIDD / 128, N_NODES / 128), 256>>>(
        feat1, W2, P, nullptr, N_NODES, HIDD, HIDD, nullptr, nullptr);
    sgemm<128, 128, 8, 8, 8, 2><<<dim3(HIDD / 128, N_NODES / 128), 256>>>(
        w, P, featOut, nullptr, N_NODES, HIDD, N_NODES, rinv, b2);

    // gc3: P3 = feat@W3; hid = rinv*(w@P3) + b3; code = tanh(hid)
    sgemm<32, 64, 8, 2, 4, 0><<<dim3(CODE / 64, N_NODES / 32), 256>>>(
        featOut, W3, P3, nullptr, N_NODES, CODE, HIDD, nullptr, nullptr);
    sgemm<32, 64, 8, 2, 4, 3><<<dim3(CODE / 64, N_NODES / 32), 256>>>(
        w, P3, hidOut, codeOut, N_NODES, CODE, N_NODES, rinv, b3);
}

// round 5
// speedup vs baseline: 3.9653x; 3.9653x over previous
#include <cuda_runtime.h>
#include <cuda_bf16.h>
#include <math.h>
#include <stdint.h>

#define N_NODES 2048
#define TXT     1386
#define HIDD    4096
#define CODE    64
#define XWORDS  44   // ceil(1386/32)

// ===================== device scratch (no allocation allowed) ===============
__device__ unsigned       g_xb[N_NODES * XWORDS];
__device__ float          g_w [(size_t)N_NODES * N_NODES];     // fp32 adj (0/1/2)
__device__ __nv_bfloat16  g_wb[(size_t)N_NODES * N_NODES];     // bf16 adj (exact)
__device__ int            g_deg[N_NODES];
__device__ float          g_rinv[N_NODES];
__device__ float          g_P  [(size_t)N_NODES * HIDD];       // P1 / P2 fp32
__device__ __nv_bfloat16  g_BThi[(size_t)HIDD * N_NODES];      // B^T hi
__device__ __nv_bfloat16  g_BTlo[(size_t)HIDD * N_NODES];      // B^T lo
__device__ __nv_bfloat16  g_f1hi[(size_t)N_NODES * HIDD];      // feat1 hi
__device__ __nv_bfloat16  g_f1lo[(size_t)N_NODES * HIDD];      // feat1 lo
__device__ __nv_bfloat16  g_W2Thi[(size_t)HIDD * HIDD];        // W2^T hi
__device__ __nv_bfloat16  g_W2Tlo[(size_t)HIDD * HIDD];        // W2^T lo
__device__ float          g_P3[(size_t)N_NODES * CODE];
__device__ float          g_part[8 * (size_t)N_NODES * CODE];  // split-K partials

// ===================== PTX helpers (plain sm_100 -- NO tcgen05) ============
__device__ __forceinline__ uint32_t smem_u32(const void* p) {
    uint32_t a;
    asm("{ .reg .u64 t; cvta.to.shared.u64 t, %1; cvt.u32.u64 %0, t; }" : "=r"(a) : "l"(p));
    return a;
}
__device__ __forceinline__ void cp16(uint32_t s, const void* g) {
    asm volatile("cp.async.cg.shared.global [%0], [%1], 16;"
        :: "r"(s), "l"(__cvta_generic_to_global(g)) : "memory");
}
#define CP_COMMIT() asm volatile("cp.async.commit_group;" ::: "memory")
#define CP_WAIT1()  asm volatile("cp.async.wait_group 1;" ::: "memory")
#define CP_WAIT0()  asm volatile("cp.async.wait_group 0;" ::: "memory")

__device__ __forceinline__ void ldmx4(uint32_t* r, uint32_t addr) {
    asm volatile("ldmatrix.sync.aligned.m8n8.x4.shared.b16 {%0,%1,%2,%3}, [%4];"
        : "=r"(r[0]), "=r"(r[1]), "=r"(r[2]), "=r"(r[3]) : "r"(addr));
}
__device__ __forceinline__ void mma16816(float* c, const uint32_t* a, const uint32_t* b) {
    asm volatile("mma.sync.aligned.m16n8k16.row.col.f32.bf16.bf16.f32 "
        "{%0,%1,%2,%3}, {%4,%5,%6,%7}, {%8,%9}, {%0,%1,%2,%3};"
        : "+f"(c[0]), "+f"(c[1]), "+f"(c[2]), "+f"(c[3])
        : "r"(a[0]), "r"(a[1]), "r"(a[2]), "r"(a[3]), "r"(b[0]), "r"(b[1]));
}

// ===================== K1: bit pack + zero degree ==========================
__global__ void pack_bits(const float* __restrict__ x) {
    int row = blockIdx.x;
    int w   = threadIdx.x;
    if (w == 0) g_deg[row] = 0;
    if (w < XWORDS) {
        unsigned bits = 0;
        int base = w * 32;
        #pragma unroll 8
        for (int b = 0; b < 32; b++) {
            int c = base + b;
            if (c < TXT && x[(size_t)row * TXT + c] != 0.0f) bits |= (1u << b);
        }
        g_xb[row * XWORDS + w] = bits;
    }
}

// ===================== K2: adjacency (fp32 + bf16) =========================
#define AT 64
__global__ void build_adj() {
    __shared__ unsigned aw[AT * XWORDS];
    __shared__ unsigned bw[AT * XWORDS];
    __shared__ int sdeg[AT];
    const int bi = blockIdx.y * AT;
    const int bj = blockIdx.x * AT;
    const int tid = threadIdx.x;

    for (int idx = tid; idx < AT * XWORDS; idx += 256) {
        int r = idx / XWORDS, c = idx % XWORDS;
        aw[idx] = g_xb[(bi + r) * XWORDS + c];
        bw[idx] = g_xb[(bj + r) * XWORDS + c];
    }
    if (tid < AT) sdeg[tid] = 0;
    __syncthreads();

    const int tx = tid % 16, ty = tid / 16;
    #pragma unroll
    for (int ii = 0; ii < 4; ii++) {
        const int i = ty * 4 + ii;
        int dsum = 0;
        #pragma unroll
        for (int jj = 0; jj < 4; jj++) {
            const int j = tx * 4 + jj;
            int cnt = 0;
            #pragma unroll 4
            for (int k = 0; k < XWORDS; k++)
                cnt += __popc(aw[i * XWORDS + k] & bw[j * XWORDS + k]);
            int wv = (cnt > 0 ? 1 : 0) + ((bi + i) == (bj + j) ? 1 : 0);
            size_t o = (size_t)(bi + i) * N_NODES + (bj + j);
            g_w[o]  = (float)wv;
            g_wb[o] = __float2bfloat16((float)wv);   // exact (0/1/2)
            dsum += wv;
        }
        atomicAdd(&sdeg[i], dsum);
    }
    __syncthreads();
    if (tid < AT) atomicAdd(&g_deg[bi + tid], sdeg[tid]);
}

__global__ void compute_rinv() {
    int i = blockIdx.x * 256 + threadIdx.x;
    if (i < N_NODES) g_rinv[i] = 1.0f / (float)g_deg[i];
}

// ===================== K4: P1 = x @ W1 via set-bit gather ==================
__global__ void xw1_kernel(const float* __restrict__ W1) {
    __shared__ int idxs[1392];
    __shared__ int nidx;
    const int row = blockIdx.x;
    const int tid = threadIdx.x;
    if (tid == 0) {
        int n = 0;
        #pragma unroll 4
        for (int w = 0; w < XWORDS; w++) {
            unsigned b = g_xb[row * XWORDS + w];
            while (b) { int bit = __ffs(b) - 1; idxs[n++] = w * 32 + bit; b &= b - 1; }
        }
        nidx = n;
    }
    __syncthreads();

    float acc[16];
    #pragma unroll
    for (int j = 0; j < 16; j++) acc[j] = 0.0f;

    const int n = nidx;
    for (int t = 0; t < n; t++) {
        const float* wr = W1 + (size_t)idxs[t] * HIDD + tid;
        #pragma unroll
        for (int j = 0; j < 16; j++) acc[j] += wr[j * 256];
    }
    float* out = g_P + (size_t)row * HIDD + tid;
    #pragma unroll
    for (int j = 0; j < 16; j++) out[j * 256] = acc[j];
}

// ===================== transpose + bf16 hi/lo split ========================
__global__ void tsplit(const float* __restrict__ in,
                       __nv_bfloat16* __restrict__ oh, __nv_bfloat16* __restrict__ ol,
                       int R, int C) {
    __shared__ float t[32][33];
    const int c0 = blockIdx.x * 32, r0 = blockIdx.y * 32;
    const int tx = threadIdx.x, ty = threadIdx.y;
    #pragma unroll
    for (int j = ty; j < 32; j += 8)
        t[j][tx] = in[(size_t)(r0 + j) * C + c0 + tx];
    __syncthreads();
    #pragma unroll
    for (int j = ty; j < 32; j += 8) {
        float v = t[tx][j];
        __nv_bfloat16 h = __float2bfloat16(v);
        float l = v - __bfloat162float(h);
        size_t o = (size_t)(c0 + j) * R + r0 + tx;
        oh[o] = h;
        ol[o] = __float2bfloat16(l);
    }
}

// ===================== mma.sync split-bf16 GEMM ============================
// C[2048, NC] = A @ B^T ; A row-major [M,K] bf16 hi[,lo], B^T row-major [NC,K].
// TERMS==2: C = Ahi@(Bhi+Blo)       TERMS==3: + Alo@Bhi
// MODE 0: write Cf fp32 | MODE 1: rsc/bias then hi/lo bf16 | MODE 2: relu, fp32
// Block 128x128, BK=32, 8 warps of 64x32, cp.async double buffer.
template<int TERMS, int MODE>
__global__ __launch_bounds__(256)
void mma_gemm(const __nv_bfloat16* __restrict__ Ahi, const __nv_bfloat16* __restrict__ Alo,
              const __nv_bfloat16* __restrict__ Bhi, const __nv_bfloat16* __restrict__ Blo,
              float* __restrict__ Cf,
              __nv_bfloat16* __restrict__ Chi, __nv_bfloat16* __restrict__ Clo,
              int K, int NC,
              const float* __restrict__ rsc, const float* __restrict__ bias)
{
    extern __shared__ __nv_bfloat16 smem[];
    constexpr int STRIDE = 40;                 // 32 + 8 pad (bf16 elems)
    constexpr int OPEL   = 128 * STRIDE;       // elems per operand tile
    constexpr int OFF_AHI = 0;
    constexpr int OFF_ALO = OPEL;              // used only if TERMS==3
    constexpr int OFF_BHI = (TERMS == 3 ? 2 : 1) * OPEL;
    constexpr int OFF_BLO = OFF_BHI + OPEL;
    constexpr int SS      = OFF_BLO + OPEL;    // elems per stage

    const int tid = threadIdx.x;
    const int w   = tid >> 5;
    const int l   = tid & 31;
    const int wm  = w >> 2;                    // 0..1
    const int wn  = w & 3;                     // 0..3
    const int bm  = blockIdx.y * 128;
    const int bn  = blockIdx.x * 128;

    const uint32_t smb = smem_u32(smem);

    auto load_stage = [&](int st, int k0) {
        const uint32_t sb = smb + (uint32_t)st * SS * 2;
        #pragma unroll
        for (int it = 0; it < 2; it++) {
            int idx = tid + it * 256;
            int r = idx >> 2, c = idx & 3;
            uint32_t so = (uint32_t)(r * STRIDE + c * 8) * 2;
            cp16(sb + OFF_AHI * 2 + so, Ahi + (size_t)(bm + r) * K + k0 + c * 8);
            if (TERMS == 3)
                cp16(sb + OFF_ALO * 2 + so, Alo + (size_t)(bm + r) * K + k0 + c * 8);
            cp16(sb + OFF_BHI * 2 + so, Bhi + (size_t)(bn + r) * K + k0 + c * 8);
            cp16(sb + OFF_BLO * 2 + so, Blo + (size_t)(bn + r) * K + k0 + c * 8);
        }
        CP_COMMIT();
    };

    float acc[4][4][4];
    #pragma unroll
    for (int i = 0; i < 4; i++)
        #pragma unroll
        for (int j = 0; j < 4; j++)
            #pragma unroll
            for (int e = 0; e < 4; e++) acc[i][j][e] = 0.0f;

    load_stage(0, 0);

    // per-thread ldmatrix base offsets (bytes, within a stage)
    const uint32_t a_off = (uint32_t)((wm * 64 + (l & 15)) * STRIDE + (l >> 4) * 8) * 2;
    const uint32_t b_off = (uint32_t)((wn * 32 + (l & 15)) * STRIDE + (l >> 4) * 8) * 2;

    const int NK = K >> 5;
    for (int kt = 0; kt < NK; kt++) {
        const int cur = kt & 1;
        if (kt + 1 < NK) { load_stage(cur ^ 1, (kt + 1) << 5); CP_WAIT1(); }
        else             { CP_WAIT0(); }
        __syncthreads();

        const uint32_t sb = smb + (uint32_t)cur * SS * 2;
        #pragma unroll
        for (int ks = 0; ks < 2; ks++) {
            const uint32_t ko = (uint32_t)ks * 32;     // 16 bf16 = 32 bytes
            uint32_t ahi[4][4];
            #pragma unroll
            for (int mt = 0; mt < 4; mt++)
                ldmx4(ahi[mt], sb + OFF_AHI * 2 + a_off + (uint32_t)(mt * 16 * STRIDE) * 2 + ko);

            uint32_t bhi[4][2], blo[4][2];
            #pragma unroll
            for (int np = 0; np < 2; np++) {
                uint32_t r[4];
                ldmx4(r, sb + OFF_BHI * 2 + b_off + (uint32_t)(np * 16 * STRIDE) * 2 + ko);
                bhi[np * 2][0] = r[0]; bhi[np * 2 + 1][0] = r[1];
                bhi[np * 2][1] = r[2]; bhi[np * 2 + 1][1] = r[3];
                ldmx4(r, sb + OFF_BLO * 2 + b_off + (uint32_t)(np * 16 * STRIDE) * 2 + ko);
                blo[np * 2][0] = r[0]; blo[np * 2 + 1][0] = r[1];
                blo[np * 2][1] = r[2]; blo[np * 2 + 1][1] = r[3];
            }

            #pragma unroll
            for (int mt = 0; mt < 4; mt++)
                #pragma unroll
                for (int nt = 0; nt < 4; nt++) {
                    mma16816(acc[mt][nt], ahi[mt], bhi[nt]);
                    mma16816(acc[mt][nt], ahi[mt], blo[nt]);
                }

            if (TERMS == 3) {
                uint32_t alo[4][4];
                #pragma unroll
                for (int mt = 0; mt < 4; mt++)
                    ldmx4(alo[mt], sb + OFF_ALO * 2 + a_off + (uint32_t)(mt * 16 * STRIDE) * 2 + ko);
                #pragma unroll
                for (int mt = 0; mt < 4; mt++)
                    #pragma unroll
                    for (int nt = 0; nt < 4; nt++)
                        mma16816(acc[mt][nt], alo[mt], bhi[nt]);
            }
        }
        __syncthreads();
    }

    // ---- epilogue (register-level, fused) ---------------------------------
    #pragma unroll
    for (int mt = 0; mt < 4; mt++) {
        const int row0 = bm + wm * 64 + mt * 16 + (l >> 2);
        float rs0 = 1.0f, rs1 = 1.0f;
        if (MODE >= 1) { rs0 = rsc[row0]; rs1 = rsc[row0 + 8]; }
        #pragma unroll
        for (int nt = 0; nt < 4; nt++) {
            const int col = bn + wn * 32 + nt * 8 + (l & 3) * 2;
            float v0 = acc[mt][nt][0], v1 = acc[mt][nt][1];
            float v2 = acc[mt][nt][2], v3 = acc[mt][nt][3];
            if (MODE >= 1) {
                const float bb0 = bias[col], bb1 = bias[col + 1];
                v0 = v0 * rs0 + bb0; v1 = v1 * rs0 + bb1;
                v2 = v2 * rs1 + bb0; v3 = v3 * rs1 + bb1;
            }
            if (MODE == 2) {
                v0 = fmaxf(v0, 0.0f); v1 = fmaxf(v1, 0.0f);
                v2 = fmaxf(v2, 0.0f); v3 = fmaxf(v3, 0.0f);
            }
            if (MODE == 1) {
                __nv_bfloat162 h01, h23, l01, l23;
                h01.x = __float2bfloat16(v0); h01.y = __float2bfloat16(v1);
                h23.x = __float2bfloat16(v2); h23.y = __float2bfloat16(v3);
                l01.x = __float2bfloat16(v0 - __bfloat162float(h01.x));
                l01.y = __float2bfloat16(v1 - __bfloat162float(h01.y));
                l23.x = __float2bfloat16(v2 - __bfloat162float(h23.x));
                l23.y = __float2bfloat16(v3 - __bfloat162float(h23.y));
                *(__nv_bfloat162*)(Chi + (size_t)row0 * NC + col)       = h01;
                *(__nv_bfloat162*)(Chi + (size_t)(row0 + 8) * NC + col) = h23;
                *(__nv_bfloat162*)(Clo + (size_t)row0 * NC + col)       = l01;
                *(__nv_bfloat162*)(Clo + (size_t)(row0 + 8) * NC + col) = l23;
            } else {
                float2 p0 = make_float2(v0, v1), p1 = make_float2(v2, v3);
                *(float2*)(Cf + (size_t)row0 * NC + col)       = p0;
                *(float2*)(Cf + (size_t)(row0 + 8) * NC + col) = p1;
            }
        }
    }
}

// ===================== split-K FFMA sgemm (gc3) ============================
template<int V>
__device__ __forceinline__ void ldvec(float* d, const float* s) {
    if constexpr (V == 4) {
        *(float4*)d = *(const float4*)s;
    } else if constexpr (V == 2) {
        *(float2*)d = *(const float2*)s;
    } else {
        #pragma unroll
        for (int i = 0; i < V; i++) d[i] = s[i];
    }
}

template<int BM, int BN, int BK, int TM, int TN>
__global__ __launch_bounds__(256)
void sgemm_sk(const float* __restrict__ A, const float* __restrict__ B,
              float* __restrict__ C, int M, int N, int K, int lda)
{
    static_assert((BM / TM) * (BN / TN) == 256, "need 256 threads");
    constexpr int ALOAD = BM * BK / 256;
    constexpr int BLOAD = BK * BN / 256;

    __shared__ float As[2][BK * BM];
    __shared__ float Bs[2][BK * BN];

    const int s = blockIdx.z;
    A += (size_t)s * K;
    B += (size_t)s * K * N;
    C += (size_t)s * M * N;

    const int tid = threadIdx.x;
    const int bm  = blockIdx.y * BM;
    const int bn  = blockIdx.x * BN;
    const int tx  = tid % (BN / TN);
    const int ty  = tid / (BN / TN);

    #pragma unroll
    for (int l = 0; l < ALOAD; l++) {
        int idx = tid + l * 256;
        int r = idx / BK, c = idx % BK;
        As[0][c * BM + r] = A[(size_t)(bm + r) * lda + c];
    }
    #pragma unroll
    for (int l = 0; l < BLOAD; l++) {
        int idx = tid + l * 256;
        int r = idx / BN, c = idx % BN;
        Bs[0][r * BN + c] = B[(size_t)r * N + bn + c];
    }
    __syncthreads();

    float acc[TM * TN];
    #pragma unroll
    for (int i = 0; i < TM * TN; i++) acc[i] = 0.0f;

    float areg[ALOAD], breg[BLOAD];
    const int nk = K / BK;
    int st = 0;

    for (int kt = 0; kt < nk; kt++) {
        if (kt + 1 < nk) {
            const int k0 = (kt + 1) * BK;
            #pragma unroll
            for (int l = 0; l < ALOAD; l++) {
                int idx = tid + l * 256;
                int r = idx / BK, c = idx % BK;
                areg[l] = A[(size_t)(bm + r) * lda + k0 + c];
            }
            #pragma unroll
            for (int l = 0; l < BLOAD; l++) {
                int idx = tid + l * 256;
                int r = idx / BN, c = idx % BN;
                breg[l] = B[(size_t)(k0 + r) * N + bn + c];
            }
        }
        #pragma unroll
        for (int kk = 0; kk < BK; kk++) {
            float fa[TM], fb[TN];
            ldvec<TM>(fa, &As[st][kk * BM + ty * TM]);
            ldvec<TN>(fb, &Bs[st][kk * BN + tx * TN]);
            #pragma unroll
            for (int i = 0; i < TM; i++)
                #pragma unroll
                for (int j = 0; j < TN; j++)
                    acc[i * TN + j] += fa[i] * fb[j];
        }
        if (kt + 1 < nk) {
            st ^= 1;
            #pragma unroll
            for (int l = 0; l < ALOAD; l++) {
                int idx = tid + l * 256;
                int r = idx / BK, c = idx % BK;
                As[st][c * BM + r] = areg[l];
            }
            #pragma unroll
            for (int l = 0; l < BLOAD; l++) {
                int idx = tid + l * 256;
                int r = idx / BN, c = idx % BN;
                Bs[st][r * BN + c] = breg[l];
            }
            __syncthreads();
        }
    }

    const int row0 = bm + ty * TM;
    const int col0 = bn + tx * TN;
    #pragma unroll
    for (int i = 0; i < TM; i++)
        #pragma unroll
        for (int j = 0; j < TN; j++)
            C[(size_t)(row0 + i) * N + col0 + j] = acc[i * TN + j];
}

// fixed-order split-K reduction with fused epilogue
template<int MODE>
__global__ void sk_reduce(const float* __restrict__ part, int M, int S,
                          float* __restrict__ C, float* __restrict__ C2,
                          const float* __restrict__ rsc, const float* __restrict__ bias) {
    int i = blockIdx.x * 256 + threadIdx.x;
    if (i >= M * CODE) return;
    int m = i >> 6, c = i & 63;
    float v = 0.0f;
    for (int s = 0; s < S; s++) v += part[(size_t)s * M * CODE + i];
    if (MODE == 3) {
        v = v * rsc[m] + bias[c];
        C[i] = v;
        C2[i] = tanhf(v);
    } else {
        C[i] = v;
    }
}

// ===================== launch ==============================================
extern "C" void kernel_launch(void* const* d_in, const int* in_sizes, int n_in,
                              void* d_out, int out_size) {
    const float* x  = (const float*)d_in[0];
    const float* W1 = (const float*)d_in[1];
    const float* b1 = (const float*)d_in[2];
    const float* W2 = (const float*)d_in[3];
    const float* b2 = (const float*)d_in[4];
    const float* W3 = (const float*)d_in[5];
    const float* b3 = (const float*)d_in[6];

    void* p;
    float *w, *rinv, *P, *P3, *part;
    __nv_bfloat16 *wb, *BThi, *BTlo, *f1hi, *f1lo, *W2Thi, *W2Tlo;
    cudaGetSymbolAddress(&p, g_w);     w     = (float*)p;
    cudaGetSymbolAddress(&p, g_wb);    wb    = (__nv_bfloat16*)p;
    cudaGetSymbolAddress(&p, g_rinv);  rinv  = (float*)p;
    cudaGetSymbolAddress(&p, g_P);     P     = (float*)p;
    cudaGetSymbolAddress(&p, g_P3);    P3    = (float*)p;
    cudaGetSymbolAddress(&p, g_part);  part  = (float*)p;
    cudaGetSymbolAddress(&p, g_BThi);  BThi  = (__nv_bfloat16*)p;
    cudaGetSymbolAddress(&p, g_BTlo);  BTlo  = (__nv_bfloat16*)p;
    cudaGetSymbolAddress(&p, g_f1hi);  f1hi  = (__nv_bfloat16*)p;
    cudaGetSymbolAddress(&p, g_f1lo);  f1lo  = (__nv_bfloat16*)p;
    cudaGetSymbolAddress(&p, g_W2Thi); W2Thi = (__nv_bfloat16*)p;
    cudaGetSymbolAddress(&p, g_W2Tlo); W2Tlo = (__nv_bfloat16*)p;

    float* featOut = (float*)d_out;
    float* hidOut  = featOut + (size_t)N_NODES * HIDD;
    float* codeOut = hidOut  + (size_t)N_NODES * CODE;

    // dynamic smem: stage elems * 2 stages * 2 bytes
    constexpr int SMEM2 = 3 * 128 * 40 * 2 * 2 * 2 / 2;   // TERMS2: 3 ops
    constexpr int SMEM3 = 4 * 128 * 40 * 2 * 2 * 2 / 2;   // TERMS3: 4 ops
    // (3*5120 elems * 2 stages * 2B = 61440 ; 4*5120*2*2 = 81920)
    cudaFuncSetAttribute(mma_gemm<2, 1>, cudaFuncAttributeMaxDynamicSharedMemorySize, SMEM2);
    cudaFuncSetAttribute(mma_gemm<3, 0>, cudaFuncAttributeMaxDynamicSharedMemorySize, SMEM3);
    cudaFuncSetAttribute(mma_gemm<2, 2>, cudaFuncAttributeMaxDynamicSharedMemorySize, SMEM2);

    // adjacency structure
    pack_bits<<<N_NODES, 64>>>(x);
    build_adj<<<dim3(N_NODES / AT, N_NODES / AT), 256>>>();
    compute_rinv<<<N_NODES / 256, 256>>>();

    // W2^T hi/lo (independent of gc1)
    tsplit<<<dim3(HIDD / 32, HIDD / 32), dim3(32, 8)>>>(W2, W2Thi, W2Tlo, HIDD, HIDD);

    // gc1: P1 = x@W1 ; feat1 = rinv*(w@P1)+b1 (hi/lo split out)
    xw1_kernel<<<N_NODES, 256>>>(W1);
    tsplit<<<dim3(HIDD / 32, N_NODES / 32), dim3(32, 8)>>>(P, BThi, BTlo, N_NODES, HIDD);
    mma_gemm<2, 1><<<dim3(HIDD / 128, N_NODES / 128), 256, SMEM2>>>(
        wb, nullptr, BThi, BTlo, nullptr, f1hi, f1lo, N_NODES, HIDD, rinv, b1);

    // gc2: P2 = feat1@W2 ; feat = relu(rinv*(w@P2)+b2) -> d_out
    mma_gemm<3, 0><<<dim3(HIDD / 128, N_NODES / 128), 256, SMEM3>>>(
        f1hi, f1lo, W2Thi, W2Tlo, P, nullptr, nullptr, HIDD, HIDD, nullptr, nullptr);
    tsplit<<<dim3(HIDD / 32, N_NODES / 32), dim3(32, 8)>>>(P, BThi, BTlo, N_NODES, HIDD);
    mma_gemm<2, 2><<<dim3(HIDD / 128, N_NODES / 128), 256, SMEM2>>>(
        wb, nullptr, BThi, BTlo, featOut, nullptr, nullptr, N_NODES, HIDD, rinv, b2);

    // gc3 with deterministic split-K (S=8)
    sgemm_sk<64, 64, 8, 4, 4><<<dim3(1, N_NODES / 64, 8), 256>>>(
        featOut, W3, part, N_NODES, CODE, HIDD / 8, HIDD);
    sk_reduce<0><<<(N_NODES * CODE + 255) / 256, 256>>>(
        part, N_NODES, 8, P3, nullptr, nullptr, nullptr);
    sgemm_sk<64, 64, 8, 4, 4><<<dim3(1, N_NODES / 64, 8), 256>>>(
        w, P3, part, N_NODES, CODE, N_NODES / 8, N_NODES);
    sk_reduce<3><<<(N_NODES * CODE + 255) / 256, 256>>>(
        part, N_NODES, 8, hidOut, codeOut, rinv, b3);
}